// round 13
// baseline (speedup 1.0000x reference)
#include <cuda_runtime.h>
#include <cuda_fp16.h>
#include <math.h>
#include <stdint.h>

#define BATCH 2
#define SEQ   2048
#define DM    1024
#define DI    2048
#define DS    16
#define XZN   (2*DI)            // 4096
#define NTOK  (BATCH*SEQ)       // 4096
#define NCH   32
#define CHL   (SEQ/NCH)         // 64
#define XD    33
#define KSPLIT 8
#define K2CH  (DI/KSPLIT)       // 256

// ---------------- scratch (static device arrays; no cudaMalloc) -----------
__device__ float g_xz   [(size_t)NTOK*XZN];
__device__ float g_xc   [(size_t)NTOK*DI];
__device__ float g_xdbl [(size_t)NTOK*XD];
__device__ float g_xpart[(size_t)KSPLIT*NTOK*XD];
__device__ float g_P    [(size_t)BATCH*NCH*DS*DI];
__device__ float g_q    [(size_t)BATCH*NCH*DS*DI];
__device__ float g_hin  [(size_t)BATCH*NCH*DS*DI];
__device__ __align__(16) __half g_xh   [(size_t)NTOK*DM];
__device__ __align__(16) __half g_winh [(size_t)DM*XZN];
__device__ __align__(16) __half g_wouth[(size_t)DI*DM];
__device__ __align__(16) __half g_yh   [(size_t)NTOK*DI];

__device__ __forceinline__ float softplusf(float x){
    return fmaxf(x, 0.f) + log1pf(__expf(-fabsf(x)));
}
__device__ __forceinline__ float siluf(float x){
    return x / (1.f + __expf(-x));
}

// ---------------- fp32 -> fp16 conversion (vectorized, n%8==0) ------------
__global__ __launch_bounds__(256) void f32_to_f16_vec(
    const float* __restrict__ s, __half* __restrict__ d, int n)
{
    int i = (blockIdx.x*256 + threadIdx.x)*8;
    if (i >= n) return;
    float4 v0 = *(const float4*)(s+i);
    float4 v1 = *(const float4*)(s+i+4);
    __half2 h[4];
    h[0] = __floats2half2_rn(v0.x, v0.y);
    h[1] = __floats2half2_rn(v0.z, v0.w);
    h[2] = __floats2half2_rn(v1.x, v1.y);
    h[3] = __floats2half2_rn(v1.z, v1.w);
    uint4 o;
    o.x = *(uint32_t*)&h[0];
    o.y = *(uint32_t*)&h[1];
    o.z = *(uint32_t*)&h[2];
    o.w = *(uint32_t*)&h[3];
    *(uint4*)(d+i) = o;
}

// ============================ fp16 tensor-core GEMM ========================
// C[M,N] = A[M,K] @ B[K,N], fp16 in / fp32 acc+out, mma.m16n8k16.
// CTA tile 256x128, BK=32, 512 threads (16 warps as 4x4), warp tile 64x32,
// 4-stage cp.async pipeline, single barrier per iter, ldmatrix x4/x4t.
// Requires M%256==0, N%128==0, K%32==0.
__device__ __forceinline__ void mma_f16(float c[4],
    uint32_t a0, uint32_t a1, uint32_t a2, uint32_t a3,
    uint32_t b0, uint32_t b1)
{
    asm volatile(
        "mma.sync.aligned.m16n8k16.row.col.f32.f16.f16.f32 "
        "{%0,%1,%2,%3},{%4,%5,%6,%7},{%8,%9},{%0,%1,%2,%3};"
        : "+f"(c[0]), "+f"(c[1]), "+f"(c[2]), "+f"(c[3])
        : "r"(a0), "r"(a1), "r"(a2), "r"(a3), "r"(b0), "r"(b1));
}
__device__ __forceinline__ void ldsm_x4(uint32_t& r0, uint32_t& r1,
                                        uint32_t& r2, uint32_t& r3, uint32_t addr)
{
    asm volatile("ldmatrix.sync.aligned.m8n8.x4.shared.b16 {%0,%1,%2,%3}, [%4];"
        : "=r"(r0), "=r"(r1), "=r"(r2), "=r"(r3) : "r"(addr));
}
__device__ __forceinline__ void ldsm_x4t(uint32_t& r0, uint32_t& r1,
                                         uint32_t& r2, uint32_t& r3, uint32_t addr)
{
    asm volatile("ldmatrix.sync.aligned.m8n8.x4.trans.shared.b16 {%0,%1,%2,%3}, [%4];"
        : "=r"(r0), "=r"(r1), "=r"(r2), "=r"(r3) : "r"(addr));
}
__device__ __forceinline__ void cp_async16(uint32_t smem, const void* g){
    asm volatile("cp.async.cg.shared.global [%0], [%1], 16;" :: "r"(smem), "l"(g));
}

#define MTILE 256
#define BKH   32
#define ASTH  40      // A smem stride (halves): 80B rows, ldmatrix conflict-free
#define BSTH  136     // B smem stride (halves)
#define STG   4
#define A_TILE_H (MTILE*ASTH)   // 10240 halves
#define B_TILE_H (BKH*BSTH)     // 4352 halves
#define GEMMH_SMEM (STG*(A_TILE_H + B_TILE_H)*2)   // 116736 bytes

__global__ __launch_bounds__(512, 1) void gemm_f16(
    const __half* __restrict__ A, const __half* __restrict__ B,
    float* __restrict__ C, int M, int N, int K)
{
    extern __shared__ __half hsmem[];
    __half* Asm = hsmem;
    __half* Bsm = hsmem + STG*A_TILE_H;
    const int tid  = threadIdx.x;
    const int lane = tid & 31;
    const int wid  = tid >> 5;          // 0..15
    const int g    = lane >> 2;
    const int tig  = lane & 3;
    const int wm   = wid >> 2;          // 0..3
    const int wn   = wid & 3;           // 0..3
    const int row0 = blockIdx.y * MTILE;
    const int col0 = blockIdx.x * 128;

    // global->shared coords: A tile [256][32]h, B tile [32][128]h
    const int ar = tid >> 1;            // A row 0..255
    const int ac = (tid & 1) * 16;      // A col (halves)
    const int br = tid >> 4;            // B k-row 0..31
    const int bc = (tid & 15) * 8;      // B col (halves), one 16B cp per thread
    const __half* Agp = A + (size_t)(row0 + ar)*K + ac;
    const __half* Bgp = B + (size_t)br*N + col0 + bc;
    const uint32_t sA = (uint32_t)__cvta_generic_to_shared(Asm);
    const uint32_t sB = (uint32_t)__cvta_generic_to_shared(Bsm);
    const uint32_t aoff = (uint32_t)(ar*ASTH + ac) * 2u;
    const uint32_t boff = (uint32_t)(br*BSTH + bc) * 2u;

    const int a_lrow = (lane & 7) + ((lane >> 3) & 1) * 8;
    const int a_lcol = (lane >> 4) * 8;
    const int b_lrow = (lane & 7) + ((lane >> 3) & 1) * 8;
    const int b_lcol = (lane >> 4) * 8;

    float acc[4][4][4];
#pragma unroll
    for (int mt = 0; mt < 4; mt++)
#pragma unroll
        for (int nt = 0; nt < 4; nt++)
#pragma unroll
            for (int i = 0; i < 4; i++) acc[mt][nt][i] = 0.f;

    const int kt = K / BKH;
    // prologue: prefetch tiles 0,1,2
#pragma unroll
    for (int p = 0; p < 3; p++) {
        int k0 = p * BKH;
        uint32_t sa = sA + (uint32_t)p*(A_TILE_H*2);
        uint32_t sb = sB + (uint32_t)p*(B_TILE_H*2);
        const __half* ag = Agp + k0;
        const __half* bg = Bgp + (size_t)k0 * N;
        cp_async16(sa + aoff,      ag);
        cp_async16(sa + aoff + 16, ag + 8);
        cp_async16(sb + boff,      bg);
        asm volatile("cp.async.commit_group;");
    }
    for (int it = 0; it < kt; it++) {
        asm volatile("cp.async.wait_group 2;");
        __syncthreads();    // orders reads of buf(it-1) before overwrite below
        if (it + 3 < kt) {
            int k0  = (it + 3) * BKH;
            int buf = (it + 3) % STG;
            const __half* ag = Agp + k0;
            const __half* bg = Bgp + (size_t)k0 * N;
            uint32_t sa = sA + (uint32_t)buf*(A_TILE_H*2);
            uint32_t sb = sB + (uint32_t)buf*(B_TILE_H*2);
            cp_async16(sa + aoff,      ag);
            cp_async16(sa + aoff + 16, ag + 8);
            cp_async16(sb + boff,      bg);
        }
        asm volatile("cp.async.commit_group;");   // always commit: exact group math
        const uint32_t sab = sA + (uint32_t)(it % STG)*(A_TILE_H*2);
        const uint32_t sbb = sB + (uint32_t)(it % STG)*(B_TILE_H*2);
#pragma unroll
        for (int kk = 0; kk < BKH; kk += 16) {
            uint32_t af[4][4];
#pragma unroll
            for (int mt = 0; mt < 4; mt++) {
                uint32_t addr = sab +
                    (uint32_t)((wm*64 + mt*16 + a_lrow)*ASTH + kk + a_lcol) * 2u;
                ldsm_x4(af[mt][0], af[mt][1], af[mt][2], af[mt][3], addr);
            }
            uint32_t bf[4][2];
#pragma unroll
            for (int np = 0; np < 2; np++) {
                uint32_t addr = sbb +
                    (uint32_t)((kk + b_lrow)*BSTH + wn*32 + np*16 + b_lcol) * 2u;
                ldsm_x4t(bf[np*2][0], bf[np*2][1], bf[np*2+1][0], bf[np*2+1][1], addr);
            }
#pragma unroll
            for (int mt = 0; mt < 4; mt++)
#pragma unroll
                for (int nt = 0; nt < 4; nt++)
                    mma_f16(acc[mt][nt], af[mt][0], af[mt][1], af[mt][2], af[mt][3],
                            bf[nt][0], bf[nt][1]);
        }
    }
#pragma unroll
    for (int mt = 0; mt < 4; mt++) {
        int r = row0 + wm*64 + mt*16 + g;
#pragma unroll
        for (int nt = 0; nt < 4; nt++) {
            int c = col0 + wn*32 + nt*8 + tig*2;
            *(float2*)&C[(size_t)r*N + c]     = make_float2(acc[mt][nt][0], acc[mt][nt][1]);
            *(float2*)&C[(size_t)(r+8)*N + c] = make_float2(acc[mt][nt][2], acc[mt][nt][3]);
        }
    }
}

// ---------------- GEMM2: fp32 split-K skinny (N=33) -----------------------
__global__ __launch_bounds__(256) void gemm2_splitk(
    const float* __restrict__ A, const float* __restrict__ B)
{
    __shared__ float As[8][128];
    __shared__ float Bs[8][36];
    const int tid  = threadIdx.x;
    const int tx   = tid & 15;
    const int ty   = tid >> 4;
    const int row0 = blockIdx.y * 128;
    const int ks   = blockIdx.z;
    const int a_row = tid >> 1;
    const int a_col = (tid & 1) * 4;
    float* C = &g_xpart[(size_t)ks*NTOK*XD];

    float acc[8][8];
#pragma unroll
    for (int i = 0; i < 8; i++)
#pragma unroll
        for (int j = 0; j < 8; j++) acc[i][j] = 0.f;

    const int kbeg = ks * K2CH, kend = kbeg + K2CH;
    for (int k0 = kbeg; k0 < kend; k0 += 8) {
        float4 av = *(const float4*)(A + (size_t)(row0 + a_row)*DI + k0 + a_col);
        As[a_col+0][a_row] = av.x;
        As[a_col+1][a_row] = av.y;
        As[a_col+2][a_row] = av.z;
        As[a_col+3][a_row] = av.w;
        for (int i = tid; i < 8*36; i += 256) {
            int bk = i / 36, bn = i % 36;
            Bs[bk][bn] = (bn < XD) ? B[(size_t)(k0+bk)*XD + bn] : 0.f;
        }
        __syncthreads();
#pragma unroll
        for (int k = 0; k < 8; k++) {
            float ar[8], br[8];
#pragma unroll
            for (int i = 0; i < 8; i++) ar[i] = As[k][ty*8 + i];
#pragma unroll
            for (int j = 0; j < 8; j++) {
                int c = tx*8 + j;
                br[j] = (c < 36) ? Bs[k][c] : 0.f;
            }
#pragma unroll
            for (int i = 0; i < 8; i++)
#pragma unroll
                for (int j = 0; j < 8; j++)
                    acc[i][j] = fmaf(ar[i], br[j], acc[i][j]);
        }
        __syncthreads();
    }
#pragma unroll
    for (int i = 0; i < 8; i++) {
        int r = row0 + ty*8 + i;
#pragma unroll
        for (int j = 0; j < 8; j++) {
            int c = tx*8 + j;
            if (c < XD) C[(size_t)r*XD + c] = acc[i][j];
        }
    }
}

__global__ __launch_bounds__(256) void reduce_xdbl()
{
    int i = blockIdx.x*256 + threadIdx.x;
    if (i >= NTOK*XD) return;
    float s = 0.f;
#pragma unroll
    for (int ks = 0; ks < KSPLIT; ks++)
        s += g_xpart[(size_t)ks*NTOK*XD + i];
    g_xdbl[i] = s;
}

// ---------------- depthwise causal conv (D_CONV=4) + bias + SiLU ----------
__global__ __launch_bounds__(256) void conv_silu_kernel(
    const float* __restrict__ conv_w, const float* __restrict__ conv_b)
{
    int idx = blockIdx.x*256 + threadIdx.x;
    if (idx >= NTOK*DI) return;
    int d   = idx % DI;
    int tok = idx / DI;
    int t   = tok % SEQ;
    float acc = conv_b[d];
#pragma unroll
    for (int j = 0; j < 4; j++) {
        int tt = t - 3 + j;
        if (tt >= 0)
            acc = fmaf(conv_w[d*4 + j], g_xz[(size_t)(tok - 3 + j)*XZN + d], acc);
    }
    g_xc[(size_t)tok*DI + d] = siluf(acc);
}

// ---------------- scan helpers -------------------------------------------
__device__ __forceinline__ void dA_fast(float r, float dA[DS])
{
    float r2 = r*r, r4 = r2*r2, r8 = r4*r4;
    dA[0]=r;      dA[1]=r2;      dA[2]=r2*r;    dA[3]=r4;
    dA[4]=r4*r;   dA[5]=r4*r2;   dA[6]=dA[2]*r4; dA[7]=r8;
#pragma unroll
    for (int s = 8; s < 16; s++) dA[s] = dA[s-8]*r8;
}

#define SCTH 256
// ---------------- scan phase A -------------------------------------------
__global__ __launch_bounds__(SCTH) void scan_phase_a(
    const float* __restrict__ A_log, const float* __restrict__ W_dt,
    const float* __restrict__ b_dt)
{
    const int b  = blockIdx.z;
    const int c  = blockIdx.y;
    const int d  = blockIdx.x*SCTH + threadIdx.x;
    const int t0 = c*CHL;
    __shared__ float sh[CHL][17];
    __shared__ float sa[SCTH][DS];
    for (int i = threadIdx.x; i < CHL*17; i += SCTH) {
        int t = i/17, j = i%17;
        sh[t][j] = g_xdbl[(size_t)(b*SEQ + t0 + t)*XD + j];
    }
    for (int i = threadIdx.x; i < SCTH*DS; i += SCTH) {
        int dd = i / DS, s = i % DS;
        sa[dd][s] = -__expf(A_log[(size_t)(blockIdx.x*SCTH + dd)*DS + s]);
    }
    __syncthreads();

    bool fast = true;
    const float a0 = sa[threadIdx.x][0];
#pragma unroll
    for (int s = 0; s < DS; s++)
        fast = fast && (fabsf(sa[threadIdx.x][s] + (float)(s+1)) < 1e-3f*(float)(s+1));
    const float wdt = W_dt[d], bdt = b_dt[d];

    float P[DS], q[DS];
#pragma unroll
    for (int s = 0; s < DS; s++) { P[s] = 1.f; q[s] = 0.f; }

    for (int t = 0; t < CHL; t++) {
        float xr = g_xc[(size_t)(b*SEQ + t0 + t)*DI + d];
        float dt = softplusf(fmaf(sh[t][0], wdt, bdt));
        float dA[DS];
        if (fast) dA_fast(__expf(dt * a0), dA);
        else {
#pragma unroll
            for (int s = 0; s < DS; s++) dA[s] = __expf(dt * sa[threadIdx.x][s]);
        }
        float dtx = dt * xr;
#pragma unroll
        for (int s = 0; s < DS; s++) {
            P[s] *= dA[s];
            q[s]  = fmaf(dA[s], q[s], dtx * sh[t][1+s]);
        }
    }
    size_t base = ((size_t)(b*NCH + c)*DS)*DI + d;
#pragma unroll
    for (int s = 0; s < DS; s++) {
        g_P[base + (size_t)s*DI] = P[s];
        g_q[base + (size_t)s*DI] = q[s];
    }
}

// ---------------- scan phase B -------------------------------------------
__global__ __launch_bounds__(128) void scan_phase_b()
{
    int idx = blockIdx.x*128 + threadIdx.x;
    int b = idx / DI, d = idx % DI;
    float h[DS];
#pragma unroll
    for (int s = 0; s < DS; s++) h[s] = 0.f;
    for (int c = 0; c < NCH; c++) {
        size_t base = ((size_t)(b*NCH + c)*DS)*DI + d;
#pragma unroll
        for (int s = 0; s < DS; s++) {
            g_hin[base + (size_t)s*DI] = h[s];
            h[s] = fmaf(g_P[base + (size_t)s*DI], h[s], g_q[base + (size_t)s*DI]);
        }
    }
}

// ---------------- scan phase C (emits y as fp16 for GEMM3) ----------------
__global__ __launch_bounds__(SCTH) void scan_phase_c(
    const float* __restrict__ A_log, const float* __restrict__ W_dt,
    const float* __restrict__ b_dt, const float* __restrict__ D_param)
{
    const int b  = blockIdx.z;
    const int c  = blockIdx.y;
    const int d  = blockIdx.x*SCTH + threadIdx.x;
    const int t0 = c*CHL;
    __shared__ float sh[CHL][XD];
    __shared__ float sa[SCTH][DS];
    for (int i = threadIdx.x; i < CHL*XD; i += SCTH) {
        int t = i/XD, j = i%XD;
        sh[t][j] = g_xdbl[(size_t)(b*SEQ + t0 + t)*XD + j];
    }
    for (int i = threadIdx.x; i < SCTH*DS; i += SCTH) {
        int dd = i / DS, s = i % DS;
        sa[dd][s] = -__expf(A_log[(size_t)(blockIdx.x*SCTH + dd)*DS + s]);
    }
    __syncthreads();

    bool fast = true;
    const float a0 = sa[threadIdx.x][0];
#pragma unroll
    for (int s = 0; s < DS; s++)
        fast = fast && (fabsf(sa[threadIdx.x][s] + (float)(s+1)) < 1e-3f*(float)(s+1));
    const float wdt = W_dt[d], bdt = b_dt[d], Dp = D_param[d];

    float h[DS];
    size_t base = ((size_t)(b*NCH + c)*DS)*DI + d;
#pragma unroll
    for (int s = 0; s < DS; s++) h[s] = g_hin[base + (size_t)s*DI];

    for (int t = 0; t < CHL; t++) {
        size_t tok = (size_t)(b*SEQ + t0 + t);
        float xr = g_xc[tok*DI + d];
        float dt = softplusf(fmaf(sh[t][0], wdt, bdt));
        float dA[DS];
        if (fast) dA_fast(__expf(dt * a0), dA);
        else {
#pragma unroll
            for (int s = 0; s < DS; s++) dA[s] = __expf(dt * sa[threadIdx.x][s]);
        }
        float dtx = dt * xr;
        float y0 = 0.f, y1 = 0.f;
#pragma unroll
        for (int s = 0; s < DS; s += 2) {
            h[s]   = fmaf(dA[s],   h[s],   dtx * sh[t][1+s]);
            h[s+1] = fmaf(dA[s+1], h[s+1], dtx * sh[t][2+s]);
            y0 = fmaf(h[s],   sh[t][17+s], y0);
            y1 = fmaf(h[s+1], sh[t][18+s], y1);
        }
        float yv = fmaf(Dp, xr, y0 + y1);
        float zv = g_xz[tok*XZN + DI + d];
        g_yh[tok*DI + d] = __float2half_rn(yv * siluf(zv));
    }
}

// ---------------- launch --------------------------------------------------
static __half *s_xh = nullptr, *s_winh = nullptr, *s_wouth = nullptr, *s_yh = nullptr;
static float  *s_xz = nullptr, *s_xc = nullptr;

extern "C" void kernel_launch(void* const* d_in, const int* in_sizes, int n_in,
                              void* d_out, int out_size)
{
    const float* x      = (const float*)d_in[0];
    const float* W_in   = (const float*)d_in[1];
    const float* conv_w = (const float*)d_in[2];
    const float* conv_b = (const float*)d_in[3];
    const float* W_x    = (const float*)d_in[4];
    const float* W_dt   = (const float*)d_in[5];
    const float* b_dt   = (const float*)d_in[6];
    const float* A_log  = (const float*)d_in[7];
    const float* D_par  = (const float*)d_in[8];
    const float* W_out  = (const float*)d_in[9];
    float* out = (float*)d_out;

    if (!s_xz) {
        cudaGetSymbolAddress((void**)&s_xz,    g_xz);
        cudaGetSymbolAddress((void**)&s_xc,    g_xc);
        cudaGetSymbolAddress((void**)&s_xh,    g_xh);
        cudaGetSymbolAddress((void**)&s_winh,  g_winh);
        cudaGetSymbolAddress((void**)&s_wouth, g_wouth);
        cudaGetSymbolAddress((void**)&s_yh,    g_yh);
        cudaFuncSetAttribute(gemm_f16,
            cudaFuncAttributeMaxDynamicSharedMemorySize, GEMMH_SMEM);
    }

    // 0) fp32 -> fp16 operand conversions
    f32_to_f16_vec<<<(NTOK*DM/8 + 255)/256, 256>>>(x,     s_xh,    NTOK*DM);
    f32_to_f16_vec<<<(DM*XZN/8 + 255)/256, 256>>>(W_in,  s_winh,  DM*XZN);
    f32_to_f16_vec<<<(DI*DM/8  + 255)/256, 256>>>(W_out, s_wouth, DI*DM);

    // 1) xz = x @ W_in  (fp16 mma, 256x128 CTA)  [4096,1024]@[1024,4096]
    gemm_f16<<<dim3(XZN/128, NTOK/MTILE), 512, GEMMH_SMEM>>>(s_xh, s_winh, s_xz, NTOK, XZN, DM);
    // 2) depthwise conv + bias + SiLU
    conv_silu_kernel<<<(NTOK*DI + 255)/256, 256>>>(conv_w, conv_b);
    // 3) x_dbl = xc @ W_x (fp32 split-K)          [4096,2048]@[2048,33]
    gemm2_splitk<<<dim3(1, NTOK/128, KSPLIT), 256>>>(s_xc, W_x);
    reduce_xdbl<<<(NTOK*XD + 255)/256, 256>>>();
    // 4) chunked selective scan
    scan_phase_a<<<dim3(DI/SCTH, NCH, BATCH), SCTH>>>(A_log, W_dt, b_dt);
    scan_phase_b<<<(BATCH*DI)/128, 128>>>();
    scan_phase_c<<<dim3(DI/SCTH, NCH, BATCH), SCTH>>>(A_log, W_dt, b_dt, D_par);
    // 5) out = y @ W_out  (fp16 mma, 256x128 CTA) [4096,2048]@[2048,1024]
    gemm_f16<<<dim3(DM/128, NTOK/MTILE), 512, GEMMH_SMEM>>>(s_yh, s_wouth, out, NTOK, DM, DI);
}

// round 14
// speedup vs baseline: 1.1197x; 1.1197x over previous
#include <cuda_runtime.h>
#include <cuda_fp16.h>
#include <math.h>
#include <stdint.h>

#define BATCH 2
#define SEQ   2048
#define DM    1024
#define DI    2048
#define DS    16
#define XZN   (2*DI)            // 4096
#define NTOK  (BATCH*SEQ)       // 4096
#define NCH   32
#define CHL   (SEQ/NCH)         // 64
#define XD    33
#define KSPLIT 8
#define K2CH  (DI/KSPLIT)       // 256

// ---------------- scratch (static device arrays; no cudaMalloc) -----------
__device__ float g_xz   [(size_t)NTOK*XZN];
__device__ float g_xc   [(size_t)NTOK*DI];
__device__ float g_xdbl [(size_t)NTOK*XD];
__device__ float g_xpart[(size_t)KSPLIT*NTOK*XD];
__device__ float g_P    [(size_t)BATCH*NCH*DS*DI];
__device__ float g_q    [(size_t)BATCH*NCH*DS*DI];
__device__ float g_hin  [(size_t)BATCH*NCH*DS*DI];
__device__ __align__(16) __half g_xh   [(size_t)NTOK*DM];
__device__ __align__(16) __half g_winh [(size_t)DM*XZN];
__device__ __align__(16) __half g_wouth[(size_t)DI*DM];
__device__ __align__(16) __half g_yh   [(size_t)NTOK*DI];

__device__ __forceinline__ float softplusf(float x){
    return fmaxf(x, 0.f) + log1pf(__expf(-fabsf(x)));
}
__device__ __forceinline__ float siluf(float x){
    return x / (1.f + __expf(-x));
}

// ---------------- fp32 -> fp16 conversion (vectorized, n%8==0) ------------
__global__ __launch_bounds__(256) void f32_to_f16_vec(
    const float* __restrict__ s, __half* __restrict__ d, int n)
{
    int i = (blockIdx.x*256 + threadIdx.x)*8;
    if (i >= n) return;
    float4 v0 = *(const float4*)(s+i);
    float4 v1 = *(const float4*)(s+i+4);
    __half2 h[4];
    h[0] = __floats2half2_rn(v0.x, v0.y);
    h[1] = __floats2half2_rn(v0.z, v0.w);
    h[2] = __floats2half2_rn(v1.x, v1.y);
    h[3] = __floats2half2_rn(v1.z, v1.w);
    uint4 o;
    o.x = *(uint32_t*)&h[0];
    o.y = *(uint32_t*)&h[1];
    o.z = *(uint32_t*)&h[2];
    o.w = *(uint32_t*)&h[3];
    *(uint4*)(d+i) = o;
}

// ============================ fp16 tensor-core GEMM ========================
// C[M,N] = A[M,K] @ B[K,N], fp16 in / fp32 acc+out, mma.m16n8k16.
// CTA 128x128, BK=32, 256 threads (8 warps 2x4), warp tile 64x32,
// 4-stage cp.async pipeline, single barrier per iter, ldmatrix x4/x4t.
__device__ __forceinline__ void mma_f16(float c[4],
    uint32_t a0, uint32_t a1, uint32_t a2, uint32_t a3,
    uint32_t b0, uint32_t b1)
{
    asm volatile(
        "mma.sync.aligned.m16n8k16.row.col.f32.f16.f16.f32 "
        "{%0,%1,%2,%3},{%4,%5,%6,%7},{%8,%9},{%0,%1,%2,%3};"
        : "+f"(c[0]), "+f"(c[1]), "+f"(c[2]), "+f"(c[3])
        : "r"(a0), "r"(a1), "r"(a2), "r"(a3), "r"(b0), "r"(b1));
}
__device__ __forceinline__ void ldsm_x4(uint32_t& r0, uint32_t& r1,
                                        uint32_t& r2, uint32_t& r3, uint32_t addr)
{
    asm volatile("ldmatrix.sync.aligned.m8n8.x4.shared.b16 {%0,%1,%2,%3}, [%4];"
        : "=r"(r0), "=r"(r1), "=r"(r2), "=r"(r3) : "r"(addr));
}
__device__ __forceinline__ void ldsm_x4t(uint32_t& r0, uint32_t& r1,
                                         uint32_t& r2, uint32_t& r3, uint32_t addr)
{
    asm volatile("ldmatrix.sync.aligned.m8n8.x4.trans.shared.b16 {%0,%1,%2,%3}, [%4];"
        : "=r"(r0), "=r"(r1), "=r"(r2), "=r"(r3) : "r"(addr));
}
__device__ __forceinline__ void cp_async16(uint32_t smem, const void* g){
    asm volatile("cp.async.cg.shared.global [%0], [%1], 16;" :: "r"(smem), "l"(g));
}

#define BKH   32
#define ASTH  40      // A smem stride (halves): 80B rows, ldmatrix conflict-free
#define BSTH  136     // B smem stride (halves)
#define STG   4
#define A_TILE_H (128*ASTH)     // 5120 halves
#define B_TILE_H (BKH*BSTH)     // 4352 halves
#define GEMMH_SMEM (STG*(A_TILE_H + B_TILE_H)*2)   // 75776 bytes

__global__ __launch_bounds__(256, 2) void gemm_f16(
    const __half* __restrict__ A, const __half* __restrict__ B,
    float* __restrict__ C, int M, int N, int K)
{
    extern __shared__ __half hsmem[];
    __half* Asm = hsmem;
    __half* Bsm = hsmem + STG*A_TILE_H;
    const int tid  = threadIdx.x;
    const int lane = tid & 31;
    const int wid  = tid >> 5;
    const int g    = lane >> 2;
    const int tig  = lane & 3;
    const int wm   = wid >> 2;
    const int wn   = wid & 3;
    const int row0 = blockIdx.y * 128;
    const int col0 = blockIdx.x * 128;

    const int ar = tid >> 1;
    const int ac = (tid & 1) * 16;
    const int br = tid >> 3;
    const int bc = (tid & 7) * 16;
    const __half* Agp = A + (size_t)(row0 + ar)*K + ac;
    const __half* Bgp = B + (size_t)br*N + col0 + bc;
    const uint32_t sA = (uint32_t)__cvta_generic_to_shared(Asm);
    const uint32_t sB = (uint32_t)__cvta_generic_to_shared(Bsm);
    const uint32_t aoff = (uint32_t)(ar*ASTH + ac) * 2u;
    const uint32_t boff = (uint32_t)(br*BSTH + bc) * 2u;

    const int a_lrow = (lane & 7) + ((lane >> 3) & 1) * 8;
    const int a_lcol = (lane >> 4) * 8;
    const int b_lrow = (lane & 7) + ((lane >> 3) & 1) * 8;
    const int b_lcol = (lane >> 4) * 8;

    float acc[4][4][4];
#pragma unroll
    for (int mt = 0; mt < 4; mt++)
#pragma unroll
        for (int nt = 0; nt < 4; nt++)
#pragma unroll
            for (int i = 0; i < 4; i++) acc[mt][nt][i] = 0.f;

    const int kt = K / BKH;
#pragma unroll
    for (int p = 0; p < 3; p++) {
        int k0 = p * BKH;
        uint32_t sa = sA + (uint32_t)p*(A_TILE_H*2);
        uint32_t sb = sB + (uint32_t)p*(B_TILE_H*2);
        const __half* ag = Agp + k0;
        const __half* bg = Bgp + (size_t)k0 * N;
        cp_async16(sa + aoff,      ag);
        cp_async16(sa + aoff + 16, ag + 8);
        cp_async16(sb + boff,      bg);
        cp_async16(sb + boff + 16, bg + 8);
        asm volatile("cp.async.commit_group;");
    }
    for (int it = 0; it < kt; it++) {
        asm volatile("cp.async.wait_group 2;");
        __syncthreads();
        if (it + 3 < kt) {
            int k0  = (it + 3) * BKH;
            int buf = (it + 3) % STG;
            const __half* ag = Agp + k0;
            const __half* bg = Bgp + (size_t)k0 * N;
            uint32_t sa = sA + (uint32_t)buf*(A_TILE_H*2);
            uint32_t sb = sB + (uint32_t)buf*(B_TILE_H*2);
            cp_async16(sa + aoff,      ag);
            cp_async16(sa + aoff + 16, ag + 8);
            cp_async16(sb + boff,      bg);
            cp_async16(sb + boff + 16, bg + 8);
        }
        asm volatile("cp.async.commit_group;");
        const uint32_t sab = sA + (uint32_t)(it % STG)*(A_TILE_H*2);
        const uint32_t sbb = sB + (uint32_t)(it % STG)*(B_TILE_H*2);
#pragma unroll
        for (int kk = 0; kk < BKH; kk += 16) {
            uint32_t af[4][4];
#pragma unroll
            for (int mt = 0; mt < 4; mt++) {
                uint32_t addr = sab +
                    (uint32_t)((wm*64 + mt*16 + a_lrow)*ASTH + kk + a_lcol) * 2u;
                ldsm_x4(af[mt][0], af[mt][1], af[mt][2], af[mt][3], addr);
            }
            uint32_t bf[4][2];
#pragma unroll
            for (int np = 0; np < 2; np++) {
                uint32_t addr = sbb +
                    (uint32_t)((kk + b_lrow)*BSTH + wn*32 + np*16 + b_lcol) * 2u;
                ldsm_x4t(bf[np*2][0], bf[np*2][1], bf[np*2+1][0], bf[np*2+1][1], addr);
            }
#pragma unroll
            for (int mt = 0; mt < 4; mt++)
#pragma unroll
                for (int nt = 0; nt < 4; nt++)
                    mma_f16(acc[mt][nt], af[mt][0], af[mt][1], af[mt][2], af[mt][3],
                            bf[nt][0], bf[nt][1]);
        }
    }
#pragma unroll
    for (int mt = 0; mt < 4; mt++) {
        int r = row0 + wm*64 + mt*16 + g;
#pragma unroll
        for (int nt = 0; nt < 4; nt++) {
            int c = col0 + wn*32 + nt*8 + tig*2;
            *(float2*)&C[(size_t)r*N + c]     = make_float2(acc[mt][nt][0], acc[mt][nt][1]);
            *(float2*)&C[(size_t)(r+8)*N + c] = make_float2(acc[mt][nt][2], acc[mt][nt][3]);
        }
    }
}

// ---------------- GEMM2: fp32 split-K skinny (N=33) -----------------------
__global__ __launch_bounds__(256) void gemm2_splitk(
    const float* __restrict__ A, const float* __restrict__ B)
{
    __shared__ float As[8][128];
    __shared__ float Bs[8][36];
    const int tid  = threadIdx.x;
    const int tx   = tid & 15;
    const int ty   = tid >> 4;
    const int row0 = blockIdx.y * 128;
    const int ks   = blockIdx.z;
    const int a_row = tid >> 1;
    const int a_col = (tid & 1) * 4;
    float* C = &g_xpart[(size_t)ks*NTOK*XD];

    float acc[8][8];
#pragma unroll
    for (int i = 0; i < 8; i++)
#pragma unroll
        for (int j = 0; j < 8; j++) acc[i][j] = 0.f;

    const int kbeg = ks * K2CH, kend = kbeg + K2CH;
    for (int k0 = kbeg; k0 < kend; k0 += 8) {
        float4 av = *(const float4*)(A + (size_t)(row0 + a_row)*DI + k0 + a_col);
        As[a_col+0][a_row] = av.x;
        As[a_col+1][a_row] = av.y;
        As[a_col+2][a_row] = av.z;
        As[a_col+3][a_row] = av.w;
        for (int i = tid; i < 8*36; i += 256) {
            int bk = i / 36, bn = i % 36;
            Bs[bk][bn] = (bn < XD) ? B[(size_t)(k0+bk)*XD + bn] : 0.f;
        }
        __syncthreads();
#pragma unroll
        for (int k = 0; k < 8; k++) {
            float ar[8], br[8];
#pragma unroll
            for (int i = 0; i < 8; i++) ar[i] = As[k][ty*8 + i];
#pragma unroll
            for (int j = 0; j < 8; j++) {
                int c = tx*8 + j;
                br[j] = (c < 36) ? Bs[k][c] : 0.f;
            }
#pragma unroll
            for (int i = 0; i < 8; i++)
#pragma unroll
                for (int j = 0; j < 8; j++)
                    acc[i][j] = fmaf(ar[i], br[j], acc[i][j]);
        }
        __syncthreads();
    }
#pragma unroll
    for (int i = 0; i < 8; i++) {
        int r = row0 + ty*8 + i;
#pragma unroll
        for (int j = 0; j < 8; j++) {
            int c = tx*8 + j;
            if (c < XD) C[(size_t)r*XD + c] = acc[i][j];
        }
    }
}

__global__ __launch_bounds__(256) void reduce_xdbl()
{
    int i = blockIdx.x*256 + threadIdx.x;
    if (i >= NTOK*XD) return;
    float s = 0.f;
#pragma unroll
    for (int ks = 0; ks < KSPLIT; ks++)
        s += g_xpart[(size_t)ks*NTOK*XD + i];
    g_xdbl[i] = s;
}

// ---------------- depthwise causal conv: 4 tokens per thread --------------
__global__ __launch_bounds__(256) void conv_silu_kernel(
    const float* __restrict__ conv_w, const float* __restrict__ conv_b)
{
    int idx = blockIdx.x*256 + threadIdx.x;          // (tok4, d)
    if (idx >= (NTOK/4)*DI) return;
    int d    = idx % DI;
    int tb   = idx / DI;                             // token-block
    int tok0 = tb * 4;                               // b*SEQ + t0, t0%4==0
    int t0   = tok0 % SEQ;
    const float w0 = conv_w[d*4+0], w1 = conv_w[d*4+1];
    const float w2 = conv_w[d*4+2], w3 = conv_w[d*4+3];
    const float bb = conv_b[d];
    // rolling window: xz rows tok0-3 .. tok0+3 (guard sequence start)
    float win[7];
#pragma unroll
    for (int i = 0; i < 7; i++) {
        int t = t0 - 3 + i;
        win[i] = (t >= 0 && i < 7) ?
            ((t0 - 3 + i < SEQ) ? g_xz[(size_t)(tok0 - 3 + i)*XZN + d] : 0.f) : 0.f;
    }
#pragma unroll
    for (int j = 0; j < 4; j++) {
        // output token t0+j uses win[j..j+3] with same fmaf order as before
        float acc = bb;
        if (t0 + j - 3 >= 0) acc = fmaf(w0, win[j+0], acc);
        if (t0 + j - 2 >= 0) acc = fmaf(w1, win[j+1], acc);
        if (t0 + j - 1 >= 0) acc = fmaf(w2, win[j+2], acc);
        acc = fmaf(w3, win[j+3], acc);
        g_xc[(size_t)(tok0 + j)*DI + d] = siluf(acc);
    }
}

// ---------------- scan helpers -------------------------------------------
__device__ __forceinline__ void dA_fast(float r, float dA[DS])
{
    float r2 = r*r, r4 = r2*r2, r8 = r4*r4;
    dA[0]=r;      dA[1]=r2;      dA[2]=r2*r;    dA[3]=r4;
    dA[4]=r4*r;   dA[5]=r4*r2;   dA[6]=dA[2]*r4; dA[7]=r8;
#pragma unroll
    for (int s = 8; s < 16; s++) dA[s] = dA[s-8]*r8;
}

#define SCTH 256
// ---------------- scan phase A (P via exp(a*Σdt)) -------------------------
__global__ __launch_bounds__(SCTH) void scan_phase_a(
    const float* __restrict__ A_log, const float* __restrict__ W_dt,
    const float* __restrict__ b_dt)
{
    const int b  = blockIdx.z;
    const int c  = blockIdx.y;
    const int d  = blockIdx.x*SCTH + threadIdx.x;
    const int t0 = c*CHL;
    __shared__ float sh[CHL][17];
    __shared__ float sa[SCTH][DS];
    for (int i = threadIdx.x; i < CHL*17; i += SCTH) {
        int t = i/17, j = i%17;
        sh[t][j] = g_xdbl[(size_t)(b*SEQ + t0 + t)*XD + j];
    }
    for (int i = threadIdx.x; i < SCTH*DS; i += SCTH) {
        int dd = i / DS, s = i % DS;
        sa[dd][s] = -__expf(A_log[(size_t)(blockIdx.x*SCTH + dd)*DS + s]);
    }
    __syncthreads();

    bool fast = true;
    const float a0 = sa[threadIdx.x][0];
#pragma unroll
    for (int s = 0; s < DS; s++)
        fast = fast && (fabsf(sa[threadIdx.x][s] + (float)(s+1)) < 1e-3f*(float)(s+1));
    const float wdt = W_dt[d], bdt = b_dt[d];

    float S = 0.f;                // Σ dt  (P[s] = exp(a_s * S))
    float q[DS];
#pragma unroll
    for (int s = 0; s < DS; s++) q[s] = 0.f;

    for (int t = 0; t < CHL; t++) {
        float xr = g_xc[(size_t)(b*SEQ + t0 + t)*DI + d];
        float dt = softplusf(fmaf(sh[t][0], wdt, bdt));
        S += dt;
        float dA[DS];
        if (fast) dA_fast(__expf(dt * a0), dA);
        else {
#pragma unroll
            for (int s = 0; s < DS; s++) dA[s] = __expf(dt * sa[threadIdx.x][s]);
        }
        float dtx = dt * xr;
#pragma unroll
        for (int s = 0; s < DS; s++)
            q[s] = fmaf(dA[s], q[s], dtx * sh[t][1+s]);
    }
    size_t base = ((size_t)(b*NCH + c)*DS)*DI + d;
#pragma unroll
    for (int s = 0; s < DS; s++) {
        g_P[base + (size_t)s*DI] = __expf(sa[threadIdx.x][s] * S);
        g_q[base + (size_t)s*DI] = q[s];
    }
}

// ---------------- scan phase B -------------------------------------------
__global__ __launch_bounds__(128) void scan_phase_b()
{
    int idx = blockIdx.x*128 + threadIdx.x;
    int b = idx / DI, d = idx % DI;
    float h[DS];
#pragma unroll
    for (int s = 0; s < DS; s++) h[s] = 0.f;
    for (int c = 0; c < NCH; c++) {
        size_t base = ((size_t)(b*NCH + c)*DS)*DI + d;
#pragma unroll
        for (int s = 0; s < DS; s++) {
            g_hin[base + (size_t)s*DI] = h[s];
            h[s] = fmaf(g_P[base + (size_t)s*DI], h[s], g_q[base + (size_t)s*DI]);
        }
    }
}

// ---------------- scan phase C (emits y as fp16 for GEMM3) ----------------
__global__ __launch_bounds__(SCTH) void scan_phase_c(
    const float* __restrict__ A_log, const float* __restrict__ W_dt,
    const float* __restrict__ b_dt, const float* __restrict__ D_param)
{
    const int b  = blockIdx.z;
    const int c  = blockIdx.y;
    const int d  = blockIdx.x*SCTH + threadIdx.x;
    const int t0 = c*CHL;
    __shared__ float sh[CHL][XD];
    __shared__ float sa[SCTH][DS];
    for (int i = threadIdx.x; i < CHL*XD; i += SCTH) {
        int t = i/XD, j = i%XD;
        sh[t][j] = g_xdbl[(size_t)(b*SEQ + t0 + t)*XD + j];
    }
    for (int i = threadIdx.x; i < SCTH*DS; i += SCTH) {
        int dd = i / DS, s = i % DS;
        sa[dd][s] = -__expf(A_log[(size_t)(blockIdx.x*SCTH + dd)*DS + s]);
    }
    __syncthreads();

    bool fast = true;
    const float a0 = sa[threadIdx.x][0];
#pragma unroll
    for (int s = 0; s < DS; s++)
        fast = fast && (fabsf(sa[threadIdx.x][s] + (float)(s+1)) < 1e-3f*(float)(s+1));
    const float wdt = W_dt[d], bdt = b_dt[d], Dp = D_param[d];

    float h[DS];
    size_t base = ((size_t)(b*NCH + c)*DS)*DI + d;
#pragma unroll
    for (int s = 0; s < DS; s++) h[s] = g_hin[base + (size_t)s*DI];

    for (int t = 0; t < CHL; t++) {
        size_t tok = (size_t)(b*SEQ + t0 + t);
        float xr = g_xc[tok*DI + d];
        float dt = softplusf(fmaf(sh[t][0], wdt, bdt));
        float dA[DS];
        if (fast) dA_fast(__expf(dt * a0), dA);
        else {
#pragma unroll
            for (int s = 0; s < DS; s++) dA[s] = __expf(dt * sa[threadIdx.x][s]);
        }
        float dtx = dt * xr;
        float y0 = 0.f, y1 = 0.f;
#pragma unroll
        for (int s = 0; s < DS; s += 2) {
            h[s]   = fmaf(dA[s],   h[s],   dtx * sh[t][1+s]);
            h[s+1] = fmaf(dA[s+1], h[s+1], dtx * sh[t][2+s]);
            y0 = fmaf(h[s],   sh[t][17+s], y0);
            y1 = fmaf(h[s+1], sh[t][18+s], y1);
        }
        float yv = fmaf(Dp, xr, y0 + y1);
        float zv = g_xz[tok*XZN + DI + d];
        g_yh[tok*DI + d] = __float2half_rn(yv * siluf(zv));
    }
}

// ---------------- launch --------------------------------------------------
static __half *s_xh = nullptr, *s_winh = nullptr, *s_wouth = nullptr, *s_yh = nullptr;
static float  *s_xz = nullptr, *s_xc = nullptr;

extern "C" void kernel_launch(void* const* d_in, const int* in_sizes, int n_in,
                              void* d_out, int out_size)
{
    const float* x      = (const float*)d_in[0];
    const float* W_in   = (const float*)d_in[1];
    const float* conv_w = (const float*)d_in[2];
    const float* conv_b = (const float*)d_in[3];
    const float* W_x    = (const float*)d_in[4];
    const float* W_dt   = (const float*)d_in[5];
    const float* b_dt   = (const float*)d_in[6];
    const float* A_log  = (const float*)d_in[7];
    const float* D_par  = (const float*)d_in[8];
    const float* W_out  = (const float*)d_in[9];
    float* out = (float*)d_out;

    if (!s_xz) {
        cudaGetSymbolAddress((void**)&s_xz,    g_xz);
        cudaGetSymbolAddress((void**)&s_xc,    g_xc);
        cudaGetSymbolAddress((void**)&s_xh,    g_xh);
        cudaGetSymbolAddress((void**)&s_winh,  g_winh);
        cudaGetSymbolAddress((void**)&s_wouth, g_wouth);
        cudaGetSymbolAddress((void**)&s_yh,    g_yh);
        cudaFuncSetAttribute(gemm_f16,
            cudaFuncAttributeMaxDynamicSharedMemorySize, GEMMH_SMEM);
    }

    // 0) fp32 -> fp16 operand conversions
    f32_to_f16_vec<<<(NTOK*DM/8 + 255)/256, 256>>>(x,     s_xh,    NTOK*DM);
    f32_to_f16_vec<<<(DM*XZN/8 + 255)/256, 256>>>(W_in,  s_winh,  DM*XZN);
    f32_to_f16_vec<<<(DI*DM/8  + 255)/256, 256>>>(W_out, s_wouth, DI*DM);

    // 1) xz = x @ W_in  (fp16 mma, 128x128, 4-stage)  [4096,1024]@[1024,4096]
    gemm_f16<<<dim3(XZN/128, NTOK/128), 256, GEMMH_SMEM>>>(s_xh, s_winh, s_xz, NTOK, XZN, DM);
    // 2) depthwise conv + bias + SiLU (4 tokens/thread)
    conv_silu_kernel<<<((NTOK/4)*DI + 255)/256, 256>>>(conv_w, conv_b);
    // 3) x_dbl = xc @ W_x (fp32 split-K)              [4096,2048]@[2048,33]
    gemm2_splitk<<<dim3(1, NTOK/128, KSPLIT), 256>>>(s_xc, W_x);
    reduce_xdbl<<<(NTOK*XD + 255)/256, 256>>>();
    // 4) chunked selective scan
    scan_phase_a<<<dim3(DI/SCTH, NCH, BATCH), SCTH>>>(A_log, W_dt, b_dt);
    scan_phase_b<<<(BATCH*DI)/128, 128>>>();
    scan_phase_c<<<dim3(DI/SCTH, NCH, BATCH), SCTH>>>(A_log, W_dt, b_dt, D_par);
    // 5) out = y @ W_out  (fp16 mma)                   [4096,2048]@[2048,1024]
    gemm_f16<<<dim3(DM/128, NTOK/128), 256, GEMMH_SMEM>>>(s_yh, s_wouth, out, NTOK, DM, DI);
}

// round 17
// speedup vs baseline: 1.1240x; 1.0039x over previous
#include <cuda_runtime.h>
#include <cuda_fp16.h>
#include <math.h>
#include <stdint.h>

#define BATCH 2
#define SEQ   2048
#define DM    1024
#define DI    2048
#define DS    16
#define XZN   (2*DI)            // 4096
#define NTOK  (BATCH*SEQ)       // 4096
#define NCH   32
#define CHL   (SEQ/NCH)         // 64
#define XD    33
#define KSPLIT 16
#define K2CH  (DI/KSPLIT)       // 128

// ---------------- scratch (static device arrays; no cudaMalloc) -----------
__device__ float g_xz   [(size_t)NTOK*XZN];
__device__ float g_xc   [(size_t)NTOK*DI];
__device__ float g_xdbl [(size_t)NTOK*XD];
__device__ float g_xpart[(size_t)KSPLIT*NTOK*XD];
__device__ float g_P    [(size_t)BATCH*NCH*DS*DI];
__device__ float g_q    [(size_t)BATCH*NCH*DS*DI];
__device__ float g_hin  [(size_t)BATCH*NCH*DS*DI];
__device__ __align__(16) __half g_xh   [(size_t)NTOK*DM];
__device__ __align__(16) __half g_winh [(size_t)DM*XZN];
__device__ __align__(16) __half g_wouth[(size_t)DI*DM];
__device__ __align__(16) __half g_yh   [(size_t)NTOK*DI];

__device__ __forceinline__ float softplusf(float x){
    return fmaxf(x, 0.f) + log1pf(__expf(-fabsf(x)));
}
__device__ __forceinline__ float siluf(float x){
    return x / (1.f + __expf(-x));
}

// ---------------- fp32 -> fp16 conversion (vectorized, n%8==0) ------------
__global__ __launch_bounds__(256) void f32_to_f16_vec(
    const float* __restrict__ s, __half* __restrict__ d, int n)
{
    int i = (blockIdx.x*256 + threadIdx.x)*8;
    if (i >= n) return;
    float4 v0 = *(const float4*)(s+i);
    float4 v1 = *(const float4*)(s+i+4);
    __half2 h[4];
    h[0] = __floats2half2_rn(v0.x, v0.y);
    h[1] = __floats2half2_rn(v0.z, v0.w);
    h[2] = __floats2half2_rn(v1.x, v1.y);
    h[3] = __floats2half2_rn(v1.z, v1.w);
    uint4 o;
    o.x = *(uint32_t*)&h[0];
    o.y = *(uint32_t*)&h[1];
    o.z = *(uint32_t*)&h[2];
    o.w = *(uint32_t*)&h[3];
    *(uint4*)(d+i) = o;
}

// ============================ fp16 tensor-core GEMM ========================
// C[M,N] = A[M,K] @ B[K,N], fp16 in / fp32 acc+out, mma.m16n8k16.
// CTA 128x128, BK=32, 256 threads (8 warps 2x4), warp tile 64x32,
// 4-stage cp.async pipeline, single barrier per iter, ldmatrix x4/x4t.
__device__ __forceinline__ void mma_f16(float c[4],
    uint32_t a0, uint32_t a1, uint32_t a2, uint32_t a3,
    uint32_t b0, uint32_t b1)
{
    asm volatile(
        "mma.sync.aligned.m16n8k16.row.col.f32.f16.f16.f32 "
        "{%0,%1,%2,%3},{%4,%5,%6,%7},{%8,%9},{%0,%1,%2,%3};"
        : "+f"(c[0]), "+f"(c[1]), "+f"(c[2]), "+f"(c[3])
        : "r"(a0), "r"(a1), "r"(a2), "r"(a3), "r"(b0), "r"(b1));
}
__device__ __forceinline__ void ldsm_x4(uint32_t& r0, uint32_t& r1,
                                        uint32_t& r2, uint32_t& r3, uint32_t addr)
{
    asm volatile("ldmatrix.sync.aligned.m8n8.x4.shared.b16 {%0,%1,%2,%3}, [%4];"
        : "=r"(r0), "=r"(r1), "=r"(r2), "=r"(r3) : "r"(addr));
}
__device__ __forceinline__ void ldsm_x4t(uint32_t& r0, uint32_t& r1,
                                         uint32_t& r2, uint32_t& r3, uint32_t addr)
{
    asm volatile("ldmatrix.sync.aligned.m8n8.x4.trans.shared.b16 {%0,%1,%2,%3}, [%4];"
        : "=r"(r0), "=r"(r1), "=r"(r2), "=r"(r3) : "r"(addr));
}
__device__ __forceinline__ void cp_async16(uint32_t smem, const void* g){
    asm volatile("cp.async.cg.shared.global [%0], [%1], 16;" :: "r"(smem), "l"(g));
}

#define BKH   32
#define ASTH  40      // A smem stride (halves): 80B rows, ldmatrix conflict-free
#define BSTH  136     // B smem stride (halves)
#define STG   4
#define A_TILE_H (128*ASTH)     // 5120 halves
#define B_TILE_H (BKH*BSTH)     // 4352 halves
#define GEMMH_SMEM (STG*(A_TILE_H + B_TILE_H)*2)   // 75776 bytes

__global__ __launch_bounds__(256, 2) void gemm_f16(
    const __half* __restrict__ A, const __half* __restrict__ B,
    float* __restrict__ C, int M, int N, int K)
{
    extern __shared__ __half hsmem[];
    __half* Asm = hsmem;
    __half* Bsm = hsmem + STG*A_TILE_H;
    const int tid  = threadIdx.x;
    const int lane = tid & 31;
    const int wid  = tid >> 5;
    const int g    = lane >> 2;
    const int tig  = lane & 3;
    const int wm   = wid >> 2;
    const int wn   = wid & 3;
    const int row0 = blockIdx.y * 128;
    const int col0 = blockIdx.x * 128;

    const int ar = tid >> 1;
    const int ac = (tid & 1) * 16;
    const int br = tid >> 3;
    const int bc = (tid & 7) * 16;
    const __half* Agp = A + (size_t)(row0 + ar)*K + ac;
    const __half* Bgp = B + (size_t)br*N + col0 + bc;
    const uint32_t sA = (uint32_t)__cvta_generic_to_shared(Asm);
    const uint32_t sB = (uint32_t)__cvta_generic_to_shared(Bsm);
    const uint32_t aoff = (uint32_t)(ar*ASTH + ac) * 2u;
    const uint32_t boff = (uint32_t)(br*BSTH + bc) * 2u;

    const int a_lrow = (lane & 7) + ((lane >> 3) & 1) * 8;
    const int a_lcol = (lane >> 4) * 8;
    const int b_lrow = (lane & 7) + ((lane >> 3) & 1) * 8;
    const int b_lcol = (lane >> 4) * 8;

    float acc[4][4][4];
#pragma unroll
    for (int mt = 0; mt < 4; mt++)
#pragma unroll
        for (int nt = 0; nt < 4; nt++)
#pragma unroll
            for (int i = 0; i < 4; i++) acc[mt][nt][i] = 0.f;

    const int kt = K / BKH;
#pragma unroll
    for (int p = 0; p < 3; p++) {
        int k0 = p * BKH;
        uint32_t sa = sA + (uint32_t)p*(A_TILE_H*2);
        uint32_t sb = sB + (uint32_t)p*(B_TILE_H*2);
        const __half* ag = Agp + k0;
        const __half* bg = Bgp + (size_t)k0 * N;
        cp_async16(sa + aoff,      ag);
        cp_async16(sa + aoff + 16, ag + 8);
        cp_async16(sb + boff,      bg);
        cp_async16(sb + boff + 16, bg + 8);
        asm volatile("cp.async.commit_group;");
    }
    for (int it = 0; it < kt; it++) {
        asm volatile("cp.async.wait_group 2;");
        __syncthreads();
        if (it + 3 < kt) {
            int k0  = (it + 3) * BKH;
            int buf = (it + 3) % STG;
            const __half* ag = Agp + k0;
            const __half* bg = Bgp + (size_t)k0 * N;
            uint32_t sa = sA + (uint32_t)buf*(A_TILE_H*2);
            uint32_t sb = sB + (uint32_t)buf*(B_TILE_H*2);
            cp_async16(sa + aoff,      ag);
            cp_async16(sa + aoff + 16, ag + 8);
            cp_async16(sb + boff,      bg);
            cp_async16(sb + boff + 16, bg + 8);
        }
        asm volatile("cp.async.commit_group;");
        const uint32_t sab = sA + (uint32_t)(it % STG)*(A_TILE_H*2);
        const uint32_t sbb = sB + (uint32_t)(it % STG)*(B_TILE_H*2);
#pragma unroll
        for (int kk = 0; kk < BKH; kk += 16) {
            uint32_t af[4][4];
#pragma unroll
            for (int mt = 0; mt < 4; mt++) {
                uint32_t addr = sab +
                    (uint32_t)((wm*64 + mt*16 + a_lrow)*ASTH + kk + a_lcol) * 2u;
                ldsm_x4(af[mt][0], af[mt][1], af[mt][2], af[mt][3], addr);
            }
            uint32_t bf[4][2];
#pragma unroll
            for (int np = 0; np < 2; np++) {
                uint32_t addr = sbb +
                    (uint32_t)((kk + b_lrow)*BSTH + wn*32 + np*16 + b_lcol) * 2u;
                ldsm_x4t(bf[np*2][0], bf[np*2][1], bf[np*2+1][0], bf[np*2+1][1], addr);
            }
#pragma unroll
            for (int mt = 0; mt < 4; mt++)
#pragma unroll
                for (int nt = 0; nt < 4; nt++)
                    mma_f16(acc[mt][nt], af[mt][0], af[mt][1], af[mt][2], af[mt][3],
                            bf[nt][0], bf[nt][1]);
        }
    }
#pragma unroll
    for (int mt = 0; mt < 4; mt++) {
        int r = row0 + wm*64 + mt*16 + g;
#pragma unroll
        for (int nt = 0; nt < 4; nt++) {
            int c = col0 + wn*32 + nt*8 + tig*2;
            *(float2*)&C[(size_t)r*N + c]     = make_float2(acc[mt][nt][0], acc[mt][nt][1]);
            *(float2*)&C[(size_t)(r+8)*N + c] = make_float2(acc[mt][nt][2], acc[mt][nt][3]);
        }
    }
}

// ---------------- GEMM2: fp32 split-K skinny (N=33) -----------------------
__global__ __launch_bounds__(256) void gemm2_splitk(
    const float* __restrict__ A, const float* __restrict__ B)
{
    __shared__ float As[8][128];
    __shared__ float Bs[8][36];
    const int tid  = threadIdx.x;
    const int tx   = tid & 15;
    const int ty   = tid >> 4;
    const int row0 = blockIdx.y * 128;
    const int ks   = blockIdx.z;
    const int a_row = tid >> 1;
    const int a_col = (tid & 1) * 4;
    float* C = &g_xpart[(size_t)ks*NTOK*XD];

    float acc[8][8];
#pragma unroll
    for (int i = 0; i < 8; i++)
#pragma unroll
        for (int j = 0; j < 8; j++) acc[i][j] = 0.f;

    const int kbeg = ks * K2CH, kend = kbeg + K2CH;
    for (int k0 = kbeg; k0 < kend; k0 += 8) {
        float4 av = *(const float4*)(A + (size_t)(row0 + a_row)*DI + k0 + a_col);
        As[a_col+0][a_row] = av.x;
        As[a_col+1][a_row] = av.y;
        As[a_col+2][a_row] = av.z;
        As[a_col+3][a_row] = av.w;
        for (int i = tid; i < 8*36; i += 256) {
            int bk = i / 36, bn = i % 36;
            Bs[bk][bn] = (bn < XD) ? B[(size_t)(k0+bk)*XD + bn] : 0.f;
        }
        __syncthreads();
#pragma unroll
        for (int k = 0; k < 8; k++) {
            float ar[8], br[8];
#pragma unroll
            for (int i = 0; i < 8; i++) ar[i] = As[k][ty*8 + i];
#pragma unroll
            for (int j = 0; j < 8; j++) {
                int c = tx*8 + j;
                br[j] = (c < 36) ? Bs[k][c] : 0.f;
            }
#pragma unroll
            for (int i = 0; i < 8; i++)
#pragma unroll
                for (int j = 0; j < 8; j++)
                    acc[i][j] = fmaf(ar[i], br[j], acc[i][j]);
        }
        __syncthreads();
    }
#pragma unroll
    for (int i = 0; i < 8; i++) {
        int r = row0 + ty*8 + i;
#pragma unroll
        for (int j = 0; j < 8; j++) {
            int c = tx*8 + j;
            if (c < XD) C[(size_t)r*XD + c] = acc[i][j];
        }
    }
}

__global__ __launch_bounds__(256) void reduce_xdbl()
{
    int i = blockIdx.x*256 + threadIdx.x;
    if (i >= NTOK*XD) return;
    float s = 0.f;
#pragma unroll
    for (int ks = 0; ks < KSPLIT; ks++)
        s += g_xpart[(size_t)ks*NTOK*XD + i];
    g_xdbl[i] = s;
}

// ---------------- depthwise causal conv: 4 tokens per thread --------------
__global__ __launch_bounds__(256) void conv_silu_kernel(
    const float* __restrict__ conv_w, const float* __restrict__ conv_b)
{
    int idx = blockIdx.x*256 + threadIdx.x;
    if (idx >= (NTOK/4)*DI) return;
    int d    = idx % DI;
    int tb   = idx / DI;
    int tok0 = tb * 4;
    int t0   = tok0 % SEQ;
    const float w0 = conv_w[d*4+0], w1 = conv_w[d*4+1];
    const float w2 = conv_w[d*4+2], w3 = conv_w[d*4+3];
    const float bb = conv_b[d];
    float win[7];
#pragma unroll
    for (int i = 0; i < 7; i++) {
        int t = t0 - 3 + i;
        win[i] = (t >= 0 && i < 7) ?
            ((t0 - 3 + i < SEQ) ? g_xz[(size_t)(tok0 - 3 + i)*XZN + d] : 0.f) : 0.f;
    }
#pragma unroll
    for (int j = 0; j < 4; j++) {
        float acc = bb;
        if (t0 + j - 3 >= 0) acc = fmaf(w0, win[j+0], acc);
        if (t0 + j - 2 >= 0) acc = fmaf(w1, win[j+1], acc);
        if (t0 + j - 1 >= 0) acc = fmaf(w2, win[j+2], acc);
        acc = fmaf(w3, win[j+3], acc);
        g_xc[(size_t)(tok0 + j)*DI + d] = siluf(acc);
    }
}

// ---------------- scan helpers -------------------------------------------
__device__ __forceinline__ void dA_fast(float r, float dA[DS])
{
    float r2 = r*r, r4 = r2*r2, r8 = r4*r4;
    dA[0]=r;      dA[1]=r2;      dA[2]=r2*r;    dA[3]=r4;
    dA[4]=r4*r;   dA[5]=r4*r2;   dA[6]=dA[2]*r4; dA[7]=r8;
#pragma unroll
    for (int s = 8; s < 16; s++) dA[s] = dA[s-8]*r8;
}

#define SCTH 256
// ---------------- scan phase A (P via exp(a*Σdt)) -------------------------
__global__ __launch_bounds__(SCTH) void scan_phase_a(
    const float* __restrict__ A_log, const float* __restrict__ W_dt,
    const float* __restrict__ b_dt)
{
    const int b  = blockIdx.z;
    const int c  = blockIdx.y;
    const int d  = blockIdx.x*SCTH + threadIdx.x;
    const int t0 = c*CHL;
    __shared__ float sh[CHL][17];
    __shared__ float sa[SCTH][DS];
    for (int i = threadIdx.x; i < CHL*17; i += SCTH) {
        int t = i/17, j = i%17;
        sh[t][j] = g_xdbl[(size_t)(b*SEQ + t0 + t)*XD + j];
    }
    for (int i = threadIdx.x; i < SCTH*DS; i += SCTH) {
        int dd = i / DS, s = i % DS;
        sa[dd][s] = -__expf(A_log[(size_t)(blockIdx.x*SCTH + dd)*DS + s]);
    }
    __syncthreads();

    bool fast = true;
    const float a0 = sa[threadIdx.x][0];
#pragma unroll
    for (int s = 0; s < DS; s++)
        fast = fast && (fabsf(sa[threadIdx.x][s] + (float)(s+1)) < 1e-3f*(float)(s+1));
    const float wdt = W_dt[d], bdt = b_dt[d];

    float S = 0.f;
    float q[DS];
#pragma unroll
    for (int s = 0; s < DS; s++) q[s] = 0.f;

#pragma unroll 2
    for (int t = 0; t < CHL; t++) {
        float xr = g_xc[(size_t)(b*SEQ + t0 + t)*DI + d];
        float dt = softplusf(fmaf(sh[t][0], wdt, bdt));
        S += dt;
        float dA[DS];
        if (fast) dA_fast(__expf(dt * a0), dA);
        else {
#pragma unroll
            for (int s = 0; s < DS; s++) dA[s] = __expf(dt * sa[threadIdx.x][s]);
        }
        float dtx = dt * xr;
#pragma unroll
        for (int s = 0; s < DS; s++)
            q[s] = fmaf(dA[s], q[s], dtx * sh[t][1+s]);
    }
    size_t base = ((size_t)(b*NCH + c)*DS)*DI + d;
#pragma unroll
    for (int s = 0; s < DS; s++) {
        g_P[base + (size_t)s*DI] = __expf(sa[threadIdx.x][s] * S);
        g_q[base + (size_t)s*DI] = q[s];
    }
}

// ---------------- scan phase B -------------------------------------------
__global__ __launch_bounds__(128) void scan_phase_b()
{
    int idx = blockIdx.x*128 + threadIdx.x;
    int b = idx / DI, d = idx % DI;
    float h[DS];
#pragma unroll
    for (int s = 0; s < DS; s++) h[s] = 0.f;
    for (int c = 0; c < NCH; c++) {
        size_t base = ((size_t)(b*NCH + c)*DS)*DI + d;
#pragma unroll
        for (int s = 0; s < DS; s++) {
            g_hin[base + (size_t)s*DI] = h[s];
            h[s] = fmaf(g_P[base + (size_t)s*DI], h[s], g_q[base + (size_t)s*DI]);
        }
    }
}

// ---------------- scan phase C (emits y as fp16 for GEMM3) ----------------
__global__ __launch_bounds__(SCTH) void scan_phase_c(
    const float* __restrict__ A_log, const float* __restrict__ W_dt,
    const float* __restrict__ b_dt, const float* __restrict__ D_param)
{
    const int b  = blockIdx.z;
    const int c  = blockIdx.y;
    const int d  = blockIdx.x*SCTH + threadIdx.x;
    const int t0 = c*CHL;
    __shared__ float sh[CHL][XD];
    __shared__ float sa[SCTH][DS];
    for (int i = threadIdx.x; i < CHL*XD; i += SCTH) {
        int t = i/XD, j = i%XD;
        sh[t][j] = g_xdbl[(size_t)(b*SEQ + t0 + t)*XD + j];
    }
    for (int i = threadIdx.x; i < SCTH*DS; i += SCTH) {
        int dd = i / DS, s = i % DS;
        sa[dd][s] = -__expf(A_log[(size_t)(blockIdx.x*SCTH + dd)*DS + s]);
    }
    __syncthreads();

    bool fast = true;
    const float a0 = sa[threadIdx.x][0];
#pragma unroll
    for (int s = 0; s < DS; s++)
        fast = fast && (fabsf(sa[threadIdx.x][s] + (float)(s+1)) < 1e-3f*(float)(s+1));
    const float wdt = W_dt[d], bdt = b_dt[d], Dp = D_param[d];

    float h[DS];
    size_t base = ((size_t)(b*NCH + c)*DS)*DI + d;
#pragma unroll
    for (int s = 0; s < DS; s++) h[s] = g_hin[base + (size_t)s*DI];

#pragma unroll 2
    for (int t = 0; t < CHL; t++) {
        size_t tok = (size_t)(b*SEQ + t0 + t);
        float xr = g_xc[tok*DI + d];
        float dt = softplusf(fmaf(sh[t][0], wdt, bdt));
        float dA[DS];
        if (fast) dA_fast(__expf(dt * a0), dA);
        else {
#pragma unroll
            for (int s = 0; s < DS; s++) dA[s] = __expf(dt * sa[threadIdx.x][s]);
        }
        float dtx = dt * xr;
        float y0 = 0.f, y1 = 0.f;
#pragma unroll
        for (int s = 0; s < DS; s += 2) {
            h[s]   = fmaf(dA[s],   h[s],   dtx * sh[t][1+s]);
            h[s+1] = fmaf(dA[s+1], h[s+1], dtx * sh[t][2+s]);
            y0 = fmaf(h[s],   sh[t][17+s], y0);
            y1 = fmaf(h[s+1], sh[t][18+s], y1);
        }
        float yv = fmaf(Dp, xr, y0 + y1);
        float zv = g_xz[tok*XZN + DI + d];
        g_yh[tok*DI + d] = __float2half_rn(yv * siluf(zv));
    }
}

// ---------------- launch --------------------------------------------------
static __half *s_xh = nullptr, *s_winh = nullptr, *s_wouth = nullptr, *s_yh = nullptr;
static float  *s_xz = nullptr, *s_xc = nullptr;

extern "C" void kernel_launch(void* const* d_in, const int* in_sizes, int n_in,
                              void* d_out, int out_size)
{
    const float* x      = (const float*)d_in[0];
    const float* W_in   = (const float*)d_in[1];
    const float* conv_w = (const float*)d_in[2];
    const float* conv_b = (const float*)d_in[3];
    const float* W_x    = (const float*)d_in[4];
    const float* W_dt   = (const float*)d_in[5];
    const float* b_dt   = (const float*)d_in[6];
    const float* A_log  = (const float*)d_in[7];
    const float* D_par  = (const float*)d_in[8];
    const float* W_out  = (const float*)d_in[9];
    float* out = (float*)d_out;

    if (!s_xz) {
        cudaGetSymbolAddress((void**)&s_xz,    g_xz);
        cudaGetSymbolAddress((void**)&s_xc,    g_xc);
        cudaGetSymbolAddress((void**)&s_xh,    g_xh);
        cudaGetSymbolAddress((void**)&s_winh,  g_winh);
        cudaGetSymbolAddress((void**)&s_wouth, g_wouth);
        cudaGetSymbolAddress((void**)&s_yh,    g_yh);
        cudaFuncSetAttribute(gemm_f16,
            cudaFuncAttributeMaxDynamicSharedMemorySize, GEMMH_SMEM);
    }

    // 0) fp32 -> fp16 operand conversions
    f32_to_f16_vec<<<(NTOK*DM/8 + 255)/256, 256>>>(x,     s_xh,    NTOK*DM);
    f32_to_f16_vec<<<(DM*XZN/8 + 255)/256, 256>>>(W_in,  s_winh,  DM*XZN);
    f32_to_f16_vec<<<(DI*DM/8  + 255)/256, 256>>>(W_out, s_wouth, DI*DM);

    // 1) xz = x @ W_in  (fp16 mma, 128x128, 4-stage)  [4096,1024]@[1024,4096]
    gemm_f16<<<dim3(XZN/128, NTOK/128), 256, GEMMH_SMEM>>>(s_xh, s_winh, s_xz, NTOK, XZN, DM);
    // 2) depthwise conv + bias + SiLU (4 tokens/thread)
    conv_silu_kernel<<<((NTOK/4)*DI + 255)/256, 256>>>(conv_w, conv_b);
    // 3) x_dbl = xc @ W_x (fp32 split-K x16)          [4096,2048]@[2048,33]
    gemm2_splitk<<<dim3(1, NTOK/128, KSPLIT), 256>>>(s_xc, W_x);
    reduce_xdbl<<<(NTOK*XD + 255)/256, 256>>>();
    // 4) chunked selective scan (unroll-2 t-loops)
    scan_phase_a<<<dim3(DI/SCTH, NCH, BATCH), SCTH>>>(A_log, W_dt, b_dt);
    scan_phase_b<<<(BATCH*DI)/128, 128>>>();
    scan_phase_c<<<dim3(DI/SCTH, NCH, BATCH), SCTH>>>(A_log, W_dt, b_dt, D_par);
    // 5) out = y @ W_out  (fp16 mma)                   [4096,2048]@[2048,1024]
    gemm_f16<<<dim3(DM/128, NTOK/128), 256, GEMMH_SMEM>>>(s_yh, s_wouth, out, NTOK, DM, DI);
}